// round 11
// baseline (speedup 1.0000x reference)
#include <cuda_runtime.h>
#include <cuda_bf16.h>
#include <math.h>
#include <cstdint>

#define D   64
#define NC  10
#define NS  4096

__device__ __align__(16) float g_cc[NC * D];

__device__ __forceinline__ void cp_async16(float* dst_smem, const float4* src) {
    unsigned int dst = (unsigned int)__cvta_generic_to_shared(dst_smem);
    asm volatile("cp.async.cg.shared.global [%0], [%1], 16;" :: "r"(dst), "l"(src));
}
__device__ __forceinline__ float fast_sigmoid(float x) { return 1.f / (1.f + __expf(-x)); }
__device__ __forceinline__ float fast_tanh(float x) {
    float e2 = __expf(2.f * x);
    return 1.f - 2.f / (e2 + 1.f);
}

// packed f32x2 FMA: acc.(lo,hi) += a.(lo,hi) * b.(lo,hi)
__device__ __forceinline__ void fma2(unsigned long long& acc,
                                     unsigned long long a, unsigned long long b) {
    asm("fma.rn.f32x2 %0, %1, %2, %0;" : "+l"(acc) : "l"(a), "l"(b));
}
__device__ __forceinline__ float hsum2(unsigned long long a) {
    unsigned int lo = (unsigned int)(a & 0xffffffffull);
    unsigned int hi = (unsigned int)(a >> 32);
    return __uint_as_float(lo) + __uint_as_float(hi);
}

// ---------------------------------------------------------------------------
// Kernel A (iter): identical to the proven R10 version. 640 threads, 1 block.
// ---------------------------------------------------------------------------
#define SMEM_A_FLOATS 54816
#define SMEM_A_BYTES  (SMEM_A_FLOATS * 4)

template<int R, int C>
__device__ __forceinline__ void stage_async(const float* __restrict__ W, float* s, int t) {
    const float4* g4 = (const float4*)W;
    constexpr int NF4 = R * C / 4;
    #pragma unroll
    for (int f = t; f < NF4; f += 640) {
        int r = (4 * f) / C;
        int c = (4 * f) % C;
        cp_async16(s + r * (C + 4) + c, g4 + f);
    }
}

template<int ODIM, int INNER, int ACT>
__device__ __forceinline__ void mmr(const float* __restrict__ X,
                                    const float* __restrict__ sW,
                                    const float* __restrict__ B,
                                    float* __restrict__ out, int t) {
    constexpr int STR = INNER + 4;
    if (t < ODIM * 2) {
        int o  = t % ODIM;
        int n0 = (t / ODIM) * 5;
        const float* w  = sW + o * STR;
        const float* xb = X + n0 * INNER;
        float a0x=0.f,a0y=0.f,a1x=0.f,a1y=0.f,a2x=0.f,a2y=0.f,a3x=0.f,a3y=0.f,a4x=0.f,a4y=0.f;
        #pragma unroll
        for (int j = 0; j < INNER; j += 4) {
            float4 wv = *(const float4*)(w + j);
            float4 x0 = *(const float4*)(xb + j);
            float4 x1 = *(const float4*)(xb + INNER + j);
            float4 x2 = *(const float4*)(xb + 2 * INNER + j);
            float4 x3 = *(const float4*)(xb + 3 * INNER + j);
            float4 x4 = *(const float4*)(xb + 4 * INNER + j);
            a0x = fmaf(wv.x, x0.x, fmaf(wv.z, x0.z, a0x));
            a0y = fmaf(wv.y, x0.y, fmaf(wv.w, x0.w, a0y));
            a1x = fmaf(wv.x, x1.x, fmaf(wv.z, x1.z, a1x));
            a1y = fmaf(wv.y, x1.y, fmaf(wv.w, x1.w, a1y));
            a2x = fmaf(wv.x, x2.x, fmaf(wv.z, x2.z, a2x));
            a2y = fmaf(wv.y, x2.y, fmaf(wv.w, x2.w, a2y));
            a3x = fmaf(wv.x, x3.x, fmaf(wv.z, x3.z, a3x));
            a3y = fmaf(wv.y, x3.y, fmaf(wv.w, x3.w, a3y));
            a4x = fmaf(wv.x, x4.x, fmaf(wv.z, x4.z, a4x));
            a4y = fmaf(wv.y, x4.y, fmaf(wv.w, x4.w, a4y));
        }
        float bo = B[o];
        float r0 = a0x + a0y + bo, r1 = a1x + a1y + bo, r2 = a2x + a2y + bo;
        float r3 = a3x + a3y + bo, r4 = a4x + a4y + bo;
        if (ACT) {
            r0 = fmaxf(r0, 0.f); r1 = fmaxf(r1, 0.f); r2 = fmaxf(r2, 0.f);
            r3 = fmaxf(r3, 0.f); r4 = fmaxf(r4, 0.f);
        }
        out[(n0 + 0) * ODIM + o] = r0;
        out[(n0 + 1) * ODIM + o] = r1;
        out[(n0 + 2) * ODIM + o] = r2;
        out[(n0 + 3) * ODIM + o] = r3;
        out[(n0 + 4) * ODIM + o] = r4;
    }
}

template<int ODIM, int INNER, int ACT>
__device__ __forceinline__ void mmr2(const float* __restrict__ X,
                                     const float* __restrict__ sW,
                                     const float* __restrict__ B,
                                     float* __restrict__ out, int t) {
    constexpr int STR = INNER + 4;
    if (t < ODIM * 5) {
        int o  = t % ODIM;
        int n0 = (t / ODIM) * 2;
        const float* w  = sW + o * STR;
        const float* xb = X + n0 * INNER;
        float a0x=0.f,a0y=0.f,a1x=0.f,a1y=0.f;
        #pragma unroll
        for (int j = 0; j < INNER; j += 4) {
            float4 wv = *(const float4*)(w + j);
            float4 x0 = *(const float4*)(xb + j);
            float4 x1 = *(const float4*)(xb + INNER + j);
            a0x = fmaf(wv.x, x0.x, fmaf(wv.z, x0.z, a0x));
            a0y = fmaf(wv.y, x0.y, fmaf(wv.w, x0.w, a0y));
            a1x = fmaf(wv.x, x1.x, fmaf(wv.z, x1.z, a1x));
            a1y = fmaf(wv.y, x1.y, fmaf(wv.w, x1.w, a1y));
        }
        float bo = B[o];
        float r0 = a0x + a0y + bo, r1 = a1x + a1y + bo;
        if (ACT) { r0 = fmaxf(r0, 0.f); r1 = fmaxf(r1, 0.f); }
        out[(n0 + 0) * ODIM + o] = r0;
        out[(n0 + 1) * ODIM + o] = r1;
    }
}

__device__ __forceinline__ void lnw(const float* __restrict__ X,
                                    const float* __restrict__ gma,
                                    const float* __restrict__ bta,
                                    float* __restrict__ out,
                                    float* sred, int t) {
    if (t < 320) {
        int w = t >> 5, l = t & 31;
        float v0 = X[w * 64 + l], v1 = X[w * 64 + 32 + l];
        float s = v0 + v1, s2 = v0 * v0 + v1 * v1;
        #pragma unroll
        for (int off = 16; off; off >>= 1) {
            s  += __shfl_xor_sync(0xffffffffu, s, off);
            s2 += __shfl_xor_sync(0xffffffffu, s2, off);
        }
        if (l == 0) {
            float m = s * (1.f / 64.f);
            sred[w]      = m;
            sred[16 + w] = rsqrtf(s2 * (1.f / 64.f) - m * m + 1e-5f);
        }
    }
    __syncthreads();
    int n = t >> 6, ii = t & 63;
    out[t] = (X[t] - sred[n]) * sred[16 + n] * gma[ii] + bta[ii];
    __syncthreads();
}

__global__ void __launch_bounds__(640, 1)
iter_kernel(const float* __restrict__ cc0,
            const float* __restrict__ Wk, const float* __restrict__ bk,
            const float* __restrict__ Wq, const float* __restrict__ bq,
            const float* __restrict__ Wv, const float* __restrict__ bv,
            const float* __restrict__ cc_g, const float* __restrict__ cc_b,
            const float* __restrict__ W_ih, const float* __restrict__ W_hh,
            const float* __restrict__ b_ih, const float* __restrict__ b_hh,
            const float* __restrict__ ln_g, const float* __restrict__ ln_b,
            const float* __restrict__ W1, const float* __restrict__ b1,
            const float* __restrict__ W2, const float* __restrict__ b2) {
    extern __shared__ float sm[];
    float* swq  = sm;
    float* swih = sm + 4352;
    float* swhh = sm + 17408;
    float* sw1  = sm + 30464;
    float* sw2  = sm + 39168;
    float* scc  = sm + 47616;
    float* sk   = sm + 48256;
    float* sv   = sm + 48896;
    float* sq   = sm + 49536;
    float* sxu  = sm + 50176;
    float* sgi  = sm + 50816;
    float* sgh  = sm + 52736;
    float* sattn= sm + 54656;
    float* sred = sm + 54784;

    const int t  = threadIdx.x;
    const int n  = t >> 6;
    const int ii = t & 63;

    stage_async<64,  64 >(Wq,   swq,  t);
    stage_async<192, 64 >(W_ih, swih, t);
    stage_async<192, 64 >(W_hh, swhh, t);
    stage_async<128, 64 >(W1,   sw1,  t);
    stage_async<64,  128>(W2,   sw2,  t);
    asm volatile("cp.async.commit_group;");

    scc[t] = cc0[t];

    {   // k, v directly from gmem (overlaps weight stream)
        const float4* ccr = (const float4*)(cc0 + n * 64);
        const float4* wkr = (const float4*)(Wk  + ii * 64);
        const float4* wvr = (const float4*)(Wv  + ii * 64);
        float kx = 0.f, ky = 0.f, vx = 0.f, vy = 0.f;
        #pragma unroll
        for (int j = 0; j < 16; j++) {
            float4 c4 = ccr[j];
            float4 k4 = wkr[j];
            float4 v4 = wvr[j];
            kx = fmaf(c4.x, k4.x, fmaf(c4.z, k4.z, kx));
            ky = fmaf(c4.y, k4.y, fmaf(c4.w, k4.w, ky));
            vx = fmaf(c4.x, v4.x, fmaf(c4.z, v4.z, vx));
            vy = fmaf(c4.y, v4.y, fmaf(c4.w, v4.w, vy));
        }
        sk[t] = kx + ky + bk[ii];
        sv[t] = vx + vy + bv[ii];
    }
    asm volatile("cp.async.wait_group 0;" ::: "memory");
    __syncthreads();

    for (int it = 0; it < 3; it++) {
        lnw(scc, cc_g, cc_b, sxu, sred, t);
        if (t < 128)       mmr<64, 64, 0>(sxu, swq, bq, sq, t);
        else if (t < 512)  mmr<192, 64, 0>(scc, swhh, b_hh, sgh, t - 128);
        __syncthreads();

        if (t < 100) {   // attn logits
            int an = t / 10, am = t % 10;
            const float* kr = sk + an * D;
            const float* qr = sq + am * D;
            float ax = 0.f, ay = 0.f, az = 0.f, aw = 0.f;
            #pragma unroll
            for (int j = 0; j < D; j += 4) {
                float4 kv = *(const float4*)(kr + j);
                float4 qv = *(const float4*)(qr + j);
                ax = fmaf(kv.x, qv.x, ax);
                ay = fmaf(kv.y, qv.y, ay);
                az = fmaf(kv.z, qv.z, az);
                aw = fmaf(kv.w, qv.w, aw);
            }
            sattn[an * 10 + am] = ((ax + ay) + (az + aw)) * 0.125f;
        }
        __syncthreads();
        if (t < 10) {   // softmax over axis 0, +EPS
            float mx = -1e30f;
            #pragma unroll
            for (int a = 0; a < 10; a++) mx = fmaxf(mx, sattn[a * 10 + t]);
            float ss = 0.f;
            #pragma unroll
            for (int a = 0; a < 10; a++) {
                float e = __expf(sattn[a * 10 + t] - mx);
                sattn[a * 10 + t] = e;
                ss += e;
            }
            float inv = 1.f / ss;
            #pragma unroll
            for (int a = 0; a < 10; a++)
                sattn[a * 10 + t] = sattn[a * 10 + t] * inv + 1e-8f;
        }
        __syncthreads();
        {   // updates = rownorm(attn) @ v
            float u = 0.f, ss = 0.f;
            #pragma unroll
            for (int m = 0; m < 10; m++) {
                float a = sattn[n * 10 + m];
                ss += a;
                u = fmaf(a, sv[m * D + ii], u);
            }
            sxu[t] = u / ss;
        }
        __syncthreads();

        mmr<192, 64, 0>(sxu, swih, b_ih, sgi, t);
        __syncthreads();
        {   // GRU
            float ir  = sgi[n * 192 + ii];
            float iz  = sgi[n * 192 + 64 + ii];
            float in_ = sgi[n * 192 + 128 + ii];
            float hr  = sgh[n * 192 + ii];
            float hz  = sgh[n * 192 + 64 + ii];
            float hn  = sgh[n * 192 + 128 + ii];
            float r  = fast_sigmoid(ir + hr);
            float z  = fast_sigmoid(iz + hz);
            float nn = fast_tanh(in_ + r * hn);
            scc[t] = (1.f - z) * nn + z * scc[t];
        }
        __syncthreads();

        lnw(scc, ln_g, ln_b, sxu, sred, t);
        mmr2<128, 64, 1>(sxu, sw1, b1, sgi, t);
        __syncthreads();
        mmr2<64, 128, 0>(sgi, sw2, b2, sgh, t);
        __syncthreads();
        scc[t] += sgh[t];
        __syncthreads();
    }

    g_cc[t] = scc[t];
}

// ---------------------------------------------------------------------------
// Kernel B: register-direct MLP+max. thread = (slot, output dim i).
// Weight rows LDG'd straight to registers (each byte read once); cc / h via
// broadcast LDS; packed f32x2 FMAs; max over clusters stays in registers.
// 256 threads = 4 slots per block, grid = NS/4.
// ---------------------------------------------------------------------------
__global__ void __launch_bounds__(256)
mlp_kernel(const float* __restrict__ Wa, const float* __restrict__ ba,
           const float* __restrict__ Wb, const float* __restrict__ bb,
           float* __restrict__ out) {
    __shared__ __align__(16) float scc[NC * D];
    __shared__ __align__(16) float sh[4 * NC * D];

    const int t  = threadIdx.x;
    const int sl = t >> 6;                 // slot within block
    const int i  = t & 63;                 // output dim
    const int s  = (blockIdx.x << 2) + sl; // global slot

    #pragma unroll
    for (int p = t; p < 160; p += 256)
        ((float4*)scc)[p] = ((const float4*)g_cc)[p];
    __syncthreads();

    // ---- stage 1: h[nn][i] = relu(Wa[s][i,:] . cc[nn,:] + ba[s][i])
    {
        unsigned long long acc[NC];
        #pragma unroll
        for (int nn = 0; nn < NC; nn++) acc[nn] = 0ull;   // (0.f, 0.f)

        const ulonglong2* wrow = (const ulonglong2*)(Wa + ((size_t)s << 12) + (i << 6));
        const ulonglong2* cbase = (const ulonglong2*)scc;
        #pragma unroll 4
        for (int j4 = 0; j4 < 16; j4++) {
            ulonglong2 w = wrow[j4];
            #pragma unroll
            for (int nn = 0; nn < NC; nn++) {
                ulonglong2 c = cbase[nn * 16 + j4];
                fma2(acc[nn], w.x, c.x);
                fma2(acc[nn], w.y, c.y);
            }
        }
        float bav = ba[(s << 6) + i];
        #pragma unroll
        for (int nn = 0; nn < NC; nn++)
            sh[sl * 640 + nn * 64 + i] = fmaxf(hsum2(acc[nn]) + bav, 0.f);
    }
    __syncthreads();

    // ---- stage 2: out[s][i] = max_nn( Wb[s][i,:] . h[nn,:] ) + bb[s][i]
    {
        unsigned long long acc[NC];
        #pragma unroll
        for (int nn = 0; nn < NC; nn++) acc[nn] = 0ull;

        const ulonglong2* wrow = (const ulonglong2*)(Wb + ((size_t)s << 12) + (i << 6));
        const ulonglong2* hbase = (const ulonglong2*)(sh + sl * 640);
        #pragma unroll 4
        for (int j4 = 0; j4 < 16; j4++) {
            ulonglong2 w = wrow[j4];
            #pragma unroll
            for (int nn = 0; nn < NC; nn++) {
                ulonglong2 c = hbase[nn * 16 + j4];
                fma2(acc[nn], w.x, c.x);
                fma2(acc[nn], w.y, c.y);
            }
        }
        float mx = hsum2(acc[0]);
        #pragma unroll
        for (int nn = 1; nn < NC; nn++) mx = fmaxf(mx, hsum2(acc[nn]));
        out[(s << 6) + i] = mx + bb[(s << 6) + i];
    }
}

// ---------------------------------------------------------------------------
extern "C" void kernel_launch(void* const* d_in, const int* in_sizes, int n_in,
                              void* d_out, int out_size) {
    const float* cc0  = (const float*)d_in[0];
    const float* Wk   = (const float*)d_in[1];
    const float* bk   = (const float*)d_in[2];
    const float* Wq   = (const float*)d_in[3];
    const float* bq   = (const float*)d_in[4];
    const float* Wv   = (const float*)d_in[5];
    const float* bv   = (const float*)d_in[6];
    const float* cc_g = (const float*)d_in[7];
    const float* cc_b = (const float*)d_in[8];
    const float* W_ih = (const float*)d_in[9];
    const float* W_hh = (const float*)d_in[10];
    const float* b_ih = (const float*)d_in[11];
    const float* b_hh = (const float*)d_in[12];
    const float* ln_g = (const float*)d_in[13];
    const float* ln_b = (const float*)d_in[14];
    const float* W1   = (const float*)d_in[15];
    const float* b1   = (const float*)d_in[16];
    const float* W2   = (const float*)d_in[17];
    const float* b2   = (const float*)d_in[18];
    const float* Wa   = (const float*)d_in[19];
    const float* ba   = (const float*)d_in[20];
    const float* Wb   = (const float*)d_in[21];
    const float* bb   = (const float*)d_in[22];
    float* out = (float*)d_out;

    cudaFuncSetAttribute(iter_kernel,
                         cudaFuncAttributeMaxDynamicSharedMemorySize,
                         SMEM_A_BYTES);

    iter_kernel<<<1, 640, SMEM_A_BYTES>>>(cc0, Wk, bk, Wq, bq, Wv, bv,
                                          cc_g, cc_b, W_ih, W_hh, b_ih, b_hh,
                                          ln_g, ln_b, W1, b1, W2, b2);
    mlp_kernel<<<NS / 4, 256>>>(Wa, ba, Wb, bb, out);
}

// round 12
// speedup vs baseline: 1.3404x; 1.3404x over previous
#include <cuda_runtime.h>
#include <cuda_bf16.h>
#include <math.h>
#include <cstdint>

#define D   64
#define NC  10
#define NS  4096

__device__ __align__(16) float g_cc[NC * D];

__device__ __forceinline__ void cp_async16(float* dst_smem, const float4* src) {
    unsigned int dst = (unsigned int)__cvta_generic_to_shared(dst_smem);
    asm volatile("cp.async.cg.shared.global [%0], [%1], 16;" :: "r"(dst), "l"(src));
}
__device__ __forceinline__ float fast_sigmoid(float x) { return 1.f / (1.f + __expf(-x)); }
__device__ __forceinline__ float fast_tanh(float x) {
    float e2 = __expf(2.f * x);
    return 1.f - 2.f / (e2 + 1.f);
}

// packed f32x2 FMA: acc.(lo,hi) += a.(lo,hi) * b.(lo,hi)
__device__ __forceinline__ void fma2(unsigned long long& acc,
                                     unsigned long long a, unsigned long long b) {
    asm("fma.rn.f32x2 %0, %1, %2, %0;" : "+l"(acc) : "l"(a), "l"(b));
}
__device__ __forceinline__ float hsum2(unsigned long long a) {
    unsigned int lo = (unsigned int)(a & 0xffffffffull);
    unsigned int hi = (unsigned int)(a >> 32);
    return __uint_as_float(lo) + __uint_as_float(hi);
}

// ---------------------------------------------------------------------------
// Kernel A (iter): R10 structure, mm loops converted to packed f32x2.
// 640 threads, 1 block, all weights smem-resident.
// ---------------------------------------------------------------------------
#define SMEM_A_FLOATS 54816
#define SMEM_A_BYTES  (SMEM_A_FLOATS * 4)

template<int R, int C>
__device__ __forceinline__ void stage_async(const float* __restrict__ W, float* s, int t) {
    const float4* g4 = (const float4*)W;
    constexpr int NF4 = R * C / 4;
    #pragma unroll
    for (int f = t; f < NF4; f += 640) {
        int r = (4 * f) / C;
        int c = (4 * f) % C;
        cp_async16(s + r * (C + 4) + c, g4 + f);
    }
}

// 5 clusters/thread, threads = ODIM*2, packed f32x2
template<int ODIM, int INNER, int ACT>
__device__ __forceinline__ void mmr(const float* __restrict__ X,
                                    const float* __restrict__ sW,
                                    const float* __restrict__ B,
                                    float* __restrict__ out, int t) {
    constexpr int STR = INNER + 4;
    constexpr int NJ  = INNER / 4;          // ulonglong2 per activation row
    if (t < ODIM * 2) {
        int o  = t % ODIM;
        int n0 = (t / ODIM) * 5;
        const ulonglong2* w  = (const ulonglong2*)(sW + o * STR);
        const ulonglong2* xb = (const ulonglong2*)(X + n0 * INNER);
        unsigned long long a0 = 0ull, a1 = 0ull, a2 = 0ull, a3 = 0ull, a4 = 0ull;
        #pragma unroll
        for (int j = 0; j < NJ; j++) {
            ulonglong2 wv = w[j];
            ulonglong2 x0 = xb[j];
            ulonglong2 x1 = xb[NJ + j];
            ulonglong2 x2 = xb[2 * NJ + j];
            ulonglong2 x3 = xb[3 * NJ + j];
            ulonglong2 x4 = xb[4 * NJ + j];
            fma2(a0, wv.x, x0.x); fma2(a0, wv.y, x0.y);
            fma2(a1, wv.x, x1.x); fma2(a1, wv.y, x1.y);
            fma2(a2, wv.x, x2.x); fma2(a2, wv.y, x2.y);
            fma2(a3, wv.x, x3.x); fma2(a3, wv.y, x3.y);
            fma2(a4, wv.x, x4.x); fma2(a4, wv.y, x4.y);
        }
        float bo = B[o];
        float r0 = hsum2(a0) + bo, r1 = hsum2(a1) + bo, r2 = hsum2(a2) + bo;
        float r3 = hsum2(a3) + bo, r4 = hsum2(a4) + bo;
        if (ACT) {
            r0 = fmaxf(r0, 0.f); r1 = fmaxf(r1, 0.f); r2 = fmaxf(r2, 0.f);
            r3 = fmaxf(r3, 0.f); r4 = fmaxf(r4, 0.f);
        }
        out[(n0 + 0) * ODIM + o] = r0;
        out[(n0 + 1) * ODIM + o] = r1;
        out[(n0 + 2) * ODIM + o] = r2;
        out[(n0 + 3) * ODIM + o] = r3;
        out[(n0 + 4) * ODIM + o] = r4;
    }
}

// 2 clusters/thread, threads = ODIM*5, packed f32x2
template<int ODIM, int INNER, int ACT>
__device__ __forceinline__ void mmr2(const float* __restrict__ X,
                                     const float* __restrict__ sW,
                                     const float* __restrict__ B,
                                     float* __restrict__ out, int t) {
    constexpr int STR = INNER + 4;
    constexpr int NJ  = INNER / 4;
    if (t < ODIM * 5) {
        int o  = t % ODIM;
        int n0 = (t / ODIM) * 2;
        const ulonglong2* w  = (const ulonglong2*)(sW + o * STR);
        const ulonglong2* xb = (const ulonglong2*)(X + n0 * INNER);
        unsigned long long a0 = 0ull, a1 = 0ull;
        #pragma unroll
        for (int j = 0; j < NJ; j++) {
            ulonglong2 wv = w[j];
            ulonglong2 x0 = xb[j];
            ulonglong2 x1 = xb[NJ + j];
            fma2(a0, wv.x, x0.x); fma2(a0, wv.y, x0.y);
            fma2(a1, wv.x, x1.x); fma2(a1, wv.y, x1.y);
        }
        float bo = B[o];
        float r0 = hsum2(a0) + bo, r1 = hsum2(a1) + bo;
        if (ACT) { r0 = fmaxf(r0, 0.f); r1 = fmaxf(r1, 0.f); }
        out[(n0 + 0) * ODIM + o] = r0;
        out[(n0 + 1) * ODIM + o] = r1;
    }
}

__device__ __forceinline__ void lnw(const float* __restrict__ X,
                                    const float* __restrict__ gma,
                                    const float* __restrict__ bta,
                                    float* __restrict__ out,
                                    float* sred, int t) {
    if (t < 320) {
        int w = t >> 5, l = t & 31;
        float v0 = X[w * 64 + l], v1 = X[w * 64 + 32 + l];
        float s = v0 + v1, s2 = v0 * v0 + v1 * v1;
        #pragma unroll
        for (int off = 16; off; off >>= 1) {
            s  += __shfl_xor_sync(0xffffffffu, s, off);
            s2 += __shfl_xor_sync(0xffffffffu, s2, off);
        }
        if (l == 0) {
            float m = s * (1.f / 64.f);
            sred[w]      = m;
            sred[16 + w] = rsqrtf(s2 * (1.f / 64.f) - m * m + 1e-5f);
        }
    }
    __syncthreads();
    int n = t >> 6, ii = t & 63;
    out[t] = (X[t] - sred[n]) * sred[16 + n] * gma[ii] + bta[ii];
    __syncthreads();
}

__global__ void __launch_bounds__(640, 1)
iter_kernel(const float* __restrict__ cc0,
            const float* __restrict__ Wk, const float* __restrict__ bk,
            const float* __restrict__ Wq, const float* __restrict__ bq,
            const float* __restrict__ Wv, const float* __restrict__ bv,
            const float* __restrict__ cc_g, const float* __restrict__ cc_b,
            const float* __restrict__ W_ih, const float* __restrict__ W_hh,
            const float* __restrict__ b_ih, const float* __restrict__ b_hh,
            const float* __restrict__ ln_g, const float* __restrict__ ln_b,
            const float* __restrict__ W1, const float* __restrict__ b1,
            const float* __restrict__ W2, const float* __restrict__ b2) {
    extern __shared__ float sm[];
    float* swq  = sm;
    float* swih = sm + 4352;
    float* swhh = sm + 17408;
    float* sw1  = sm + 30464;
    float* sw2  = sm + 39168;
    float* scc  = sm + 47616;
    float* sk   = sm + 48256;
    float* sv   = sm + 48896;
    float* sq   = sm + 49536;
    float* sxu  = sm + 50176;
    float* sgi  = sm + 50816;
    float* sgh  = sm + 52736;
    float* sattn= sm + 54656;
    float* sred = sm + 54784;

    const int t  = threadIdx.x;
    const int n  = t >> 6;
    const int ii = t & 63;

    stage_async<64,  64 >(Wq,   swq,  t);
    stage_async<192, 64 >(W_ih, swih, t);
    stage_async<192, 64 >(W_hh, swhh, t);
    stage_async<128, 64 >(W1,   sw1,  t);
    stage_async<64,  128>(W2,   sw2,  t);
    asm volatile("cp.async.commit_group;");

    scc[t] = cc0[t];

    {   // k, v directly from gmem (overlaps weight stream)
        const float4* ccr = (const float4*)(cc0 + n * 64);
        const float4* wkr = (const float4*)(Wk  + ii * 64);
        const float4* wvr = (const float4*)(Wv  + ii * 64);
        float kx = 0.f, ky = 0.f, vx = 0.f, vy = 0.f;
        #pragma unroll
        for (int j = 0; j < 16; j++) {
            float4 c4 = ccr[j];
            float4 k4 = wkr[j];
            float4 v4 = wvr[j];
            kx = fmaf(c4.x, k4.x, fmaf(c4.z, k4.z, kx));
            ky = fmaf(c4.y, k4.y, fmaf(c4.w, k4.w, ky));
            vx = fmaf(c4.x, v4.x, fmaf(c4.z, v4.z, vx));
            vy = fmaf(c4.y, v4.y, fmaf(c4.w, v4.w, vy));
        }
        sk[t] = kx + ky + bk[ii];
        sv[t] = vx + vy + bv[ii];
    }
    asm volatile("cp.async.wait_group 0;" ::: "memory");
    __syncthreads();

    for (int it = 0; it < 3; it++) {
        lnw(scc, cc_g, cc_b, sxu, sred, t);
        if (t < 128)       mmr<64, 64, 0>(sxu, swq, bq, sq, t);
        else if (t < 512)  mmr<192, 64, 0>(scc, swhh, b_hh, sgh, t - 128);
        __syncthreads();

        if (t < 100) {   // attn logits
            int an = t / 10, am = t % 10;
            const ulonglong2* kr = (const ulonglong2*)(sk + an * D);
            const ulonglong2* qr = (const ulonglong2*)(sq + am * D);
            unsigned long long a = 0ull;
            #pragma unroll
            for (int j = 0; j < 16; j++) {
                ulonglong2 kv = kr[j];
                ulonglong2 qv = qr[j];
                fma2(a, kv.x, qv.x);
                fma2(a, kv.y, qv.y);
            }
            sattn[an * 10 + am] = hsum2(a) * 0.125f;
        }
        __syncthreads();
        if (t < 10) {   // softmax over axis 0 (column m = t), +EPS
            float mx = -1e30f;
            #pragma unroll
            for (int a = 0; a < 10; a++) mx = fmaxf(mx, sattn[a * 10 + t]);
            float ss = 0.f;
            #pragma unroll
            for (int a = 0; a < 10; a++) {
                float e = __expf(sattn[a * 10 + t] - mx);
                sattn[a * 10 + t] = e;
                ss += e;
            }
            float inv = 1.f / ss;
            #pragma unroll
            for (int a = 0; a < 10; a++)
                sattn[a * 10 + t] = sattn[a * 10 + t] * inv + 1e-8f;
        }
        __syncthreads();
        {   // updates = rownorm(attn) @ v
            float u = 0.f, ss = 0.f;
            #pragma unroll
            for (int m = 0; m < 10; m++) {
                float a = sattn[n * 10 + m];
                ss += a;
                u = fmaf(a, sv[m * D + ii], u);
            }
            sxu[t] = u / ss;
        }
        __syncthreads();

        mmr<192, 64, 0>(sxu, swih, b_ih, sgi, t);
        __syncthreads();
        {   // GRU
            float ir  = sgi[n * 192 + ii];
            float iz  = sgi[n * 192 + 64 + ii];
            float in_ = sgi[n * 192 + 128 + ii];
            float hr  = sgh[n * 192 + ii];
            float hz  = sgh[n * 192 + 64 + ii];
            float hn  = sgh[n * 192 + 128 + ii];
            float r  = fast_sigmoid(ir + hr);
            float z  = fast_sigmoid(iz + hz);
            float nn = fast_tanh(in_ + r * hn);
            scc[t] = (1.f - z) * nn + z * scc[t];
        }
        __syncthreads();

        lnw(scc, ln_g, ln_b, sxu, sred, t);
        mmr2<128, 64, 1>(sxu, sw1, b1, sgi, t);
        __syncthreads();
        mmr2<64, 128, 0>(sgi, sw2, b2, sgh, t);
        __syncthreads();
        scc[t] += sgh[t];
        __syncthreads();
    }

    g_cc[t] = scc[t];
}

// ---------------------------------------------------------------------------
// Kernel B (mlp): R7 skeleton (one block per slot, cp.async split-group
// staging) with packed f32x2 dot loops.
// ---------------------------------------------------------------------------
__global__ void __launch_bounds__(128)
mlp_kernel(const float* __restrict__ Wa, const float* __restrict__ ba,
           const float* __restrict__ Wb, const float* __restrict__ bb,
           float* __restrict__ out) {
    __shared__ __align__(16) float sWa[64 * 68];
    __shared__ __align__(16) float sWb[64 * 68];
    __shared__ __align__(16) float scc[NC * D];
    __shared__ __align__(16) float sh [NC * D];
    __shared__ float smax[128];

    const int s = blockIdx.x;
    const int t = threadIdx.x;
    const int i = t & 63;
    const int g = t >> 6;
    const size_t base = (size_t)s * (D * D);

    const float4* ga = (const float4*)(Wa + base);
    const float4* gb = (const float4*)(Wb + base);

    // Wa group first, Wb second — wait for Wa only before stage 1.
    #pragma unroll
    for (int p = 0; p < 8; p++) {
        int f = t + p * 128;
        int r = f >> 4;
        int c = (f & 15) << 2;
        cp_async16(sWa + r * 68 + c, ga + f);
    }
    asm volatile("cp.async.commit_group;");
    #pragma unroll
    for (int p = 0; p < 8; p++) {
        int f = t + p * 128;
        int r = f >> 4;
        int c = (f & 15) << 2;
        cp_async16(sWb + r * 68 + c, gb + f);
    }
    asm volatile("cp.async.commit_group;");

    float bav = __ldg(ba + (s << 6) + i);
    float bbv = __ldg(bb + (s << 6) + i);
    #pragma unroll
    for (int p = t; p < 160; p += 128)
        ((float4*)scc)[p] = ((const float4*)g_cc)[p];

    asm volatile("cp.async.wait_group 1;" ::: "memory");
    __syncthreads();

    // ---- stage 1: h[nn][i] = relu(Wa[i,:] . cc[nn,:] + ba[i]) for 5 nn
    {
        const ulonglong2* w2 = (const ulonglong2*)(sWa + i * 68);
        const ulonglong2* cb = (const ulonglong2*)(scc + g * 5 * D);
        unsigned long long a0 = 0ull, a1 = 0ull, a2 = 0ull, a3 = 0ull, a4 = 0ull;
        #pragma unroll
        for (int j = 0; j < 16; j++) {
            ulonglong2 w  = w2[j];
            ulonglong2 c0 = cb[j];
            ulonglong2 c1 = cb[16 + j];
            ulonglong2 c2 = cb[32 + j];
            ulonglong2 c3 = cb[48 + j];
            ulonglong2 c4 = cb[64 + j];
            fma2(a0, w.x, c0.x); fma2(a0, w.y, c0.y);
            fma2(a1, w.x, c1.x); fma2(a1, w.y, c1.y);
            fma2(a2, w.x, c2.x); fma2(a2, w.y, c2.y);
            fma2(a3, w.x, c3.x); fma2(a3, w.y, c3.y);
            fma2(a4, w.x, c4.x); fma2(a4, w.y, c4.y);
        }
        int n0 = g * 5;
        sh[(n0 + 0) * D + i] = fmaxf(hsum2(a0) + bav, 0.f);
        sh[(n0 + 1) * D + i] = fmaxf(hsum2(a1) + bav, 0.f);
        sh[(n0 + 2) * D + i] = fmaxf(hsum2(a2) + bav, 0.f);
        sh[(n0 + 3) * D + i] = fmaxf(hsum2(a3) + bav, 0.f);
        sh[(n0 + 4) * D + i] = fmaxf(hsum2(a4) + bav, 0.f);
    }
    asm volatile("cp.async.wait_group 0;" ::: "memory");
    __syncthreads();

    // ---- stage 2: out[nn][i] = Wb[i,:] . h[nn,:] + bb[i], max over nn
    {
        const ulonglong2* w2 = (const ulonglong2*)(sWb + i * 68);
        const ulonglong2* hb = (const ulonglong2*)(sh + g * 5 * D);
        unsigned long long a0 = 0ull, a1 = 0ull, a2 = 0ull, a3 = 0ull, a4 = 0ull;
        #pragma unroll
        for (int j = 0; j < 16; j++) {
            ulonglong2 w  = w2[j];
            ulonglong2 c0 = hb[j];
            ulonglong2 c1 = hb[16 + j];
            ulonglong2 c2 = hb[32 + j];
            ulonglong2 c3 = hb[48 + j];
            ulonglong2 c4 = hb[64 + j];
            fma2(a0, w.x, c0.x); fma2(a0, w.y, c0.y);
            fma2(a1, w.x, c1.x); fma2(a1, w.y, c1.y);
            fma2(a2, w.x, c2.x); fma2(a2, w.y, c2.y);
            fma2(a3, w.x, c3.x); fma2(a3, w.y, c3.y);
            fma2(a4, w.x, c4.x); fma2(a4, w.y, c4.y);
        }
        float m0 = fmaxf(hsum2(a0), hsum2(a1));
        float m1 = fmaxf(hsum2(a2), hsum2(a3));
        smax[t] = fmaxf(fmaxf(m0, m1), hsum2(a4)) + bbv;
    }
    __syncthreads();
    if (g == 0) out[(s << 6) + i] = fmaxf(smax[i], smax[64 + i]);
}

// ---------------------------------------------------------------------------
extern "C" void kernel_launch(void* const* d_in, const int* in_sizes, int n_in,
                              void* d_out, int out_size) {
    const float* cc0  = (const float*)d_in[0];
    const float* Wk   = (const float*)d_in[1];
    const float* bk   = (const float*)d_in[2];
    const float* Wq   = (const float*)d_in[3];
    const float* bq   = (const float*)d_in[4];
    const float* Wv   = (const float*)d_in[5];
    const float* bv   = (const float*)d_in[6];
    const float* cc_g = (const float*)d_in[7];
    const float* cc_b = (const float*)d_in[8];
    const float* W_ih = (const float*)d_in[9];
    const float* W_hh = (const float*)d_in[10];
    const float* b_ih = (const float*)d_in[11];
    const float* b_hh = (const float*)d_in[12];
    const float* ln_g = (const float*)d_in[13];
    const float* ln_b = (const float*)d_in[14];
    const float* W1   = (const float*)d_in[15];
    const float* b1   = (const float*)d_in[16];
    const float* W2   = (const float*)d_in[17];
    const float* b2   = (const float*)d_in[18];
    const float* Wa   = (const float*)d_in[19];
    const float* ba   = (const float*)d_in[20];
    const float* Wb   = (const float*)d_in[21];
    const float* bb   = (const float*)d_in[22];
    float* out = (float*)d_out;

    cudaFuncSetAttribute(iter_kernel,
                         cudaFuncAttributeMaxDynamicSharedMemorySize,
                         SMEM_A_BYTES);

    iter_kernel<<<1, 640, SMEM_A_BYTES>>>(cc0, Wk, bk, Wq, bq, Wv, bv,
                                          cc_g, cc_b, W_ih, W_hh, b_ih, b_hh,
                                          ln_g, ln_b, W1, b1, W2, b2);
    mlp_kernel<<<NS, 128>>>(Wa, ba, Wb, bb, out);
}